// round 15
// baseline (speedup 1.0000x reference)
#include <cuda_runtime.h>

#define H      512
#define HPAD   8                 // zero weight rows per matrix (for list padding)
#define TSTEPS 98
#define INW    8
#define NPIX   784
#define OUTN   10
#define NBATCH 512
#define SPB    4                 // samples per block
#define NBLK   (NBATCH / SPB)    // 128 blocks
#define NTHR   512               // thread j owns neuron j in all 3 layers
#define NWARP  (NTHR / 32)       // 16
#define MATF   ((H + HPAD) * H)  // floats per matrix in g_wt

// Transposed weights [matrix][i][j], i in [0, H+HPAD), rows >= H are ZERO:
// 0: h2h1, 1: i2h2, 2: h2h2, 3: i2h3, 4: h2h3
__device__ float g_wt[5 * MATF];

typedef unsigned long long ull;
typedef unsigned short ushort_t;

// ---------------------------------------------------------------------------
// Cephes/glibc-class expf (verified bit-identical to reference on all taus).
// ---------------------------------------------------------------------------
__device__ __forceinline__ float xla_cephes_expf(float x) {
    const float LOG2EF = 1.44269504088896341f;
    const float C1 = 0.693359375f;
    const float C2 = -2.12194440e-4f;
    const float p0 = 1.9875691500E-4f;
    const float p1 = 1.3981999507E-3f;
    const float p2 = 8.3334519073E-3f;
    const float p3 = 4.1665795894E-2f;
    const float p4 = 1.6666665459E-1f;
    const float p5 = 5.0000001201E-1f;

    x = fminf(x, 88.3762626647950f);
    x = fmaxf(x, -88.3762626647949f);

    float fx = floorf(__fadd_rn(__fmul_rn(x, LOG2EF), 0.5f));
    x = __fsub_rn(x, __fmul_rn(fx, C1));
    x = __fsub_rn(x, __fmul_rn(fx, C2));

    float z = __fmul_rn(x, x);
    float y = p0;
    y = __fadd_rn(__fmul_rn(y, x), p1);
    y = __fadd_rn(__fmul_rn(y, x), p2);
    y = __fadd_rn(__fmul_rn(y, x), p3);
    y = __fadd_rn(__fmul_rn(y, x), p4);
    y = __fadd_rn(__fmul_rn(y, x), p5);
    y = __fadd_rn(__fmul_rn(y, z), x);
    y = __fadd_rn(1.0f, y);

    int n = (int)fx;
    return __int_as_float(__float_as_int(y) + (n << 23));
}

// ALIF update, FMA-contracted (LLVM AllowFPOpFusion::Fast) — the verified
// bit-exact numeric contract from R9. DO NOT CHANGE.
__device__ __forceinline__ void alif_step(float h, float& m, float& b, float sold,
                                          float alpha, float oma, float ro, float omro,
                                          float& snew) {
    b = __fmaf_rn(ro, b, __fmul_rn(omro, sold));
    float Bth = __fmaf_rn(1.8f, b, 0.01f);
    float X = __fmaf_rn(m, alpha, __fmul_rn(oma, h));
    m = __fmaf_rn(-Bth, sold, X);
    snew = (__fsub_rn(m, Bth) > 0.0f) ? 1.0f : 0.0f;
}

// ---------------------------------------------------------------------------
// Tiled transpose into padded layout + zero the pad rows.
// grid (16,16,5), block (32,32)
// ---------------------------------------------------------------------------
__global__ void transpose5_kernel(const float* __restrict__ w0,
                                  const float* __restrict__ w1,
                                  const float* __restrict__ w2,
                                  const float* __restrict__ w3,
                                  const float* __restrict__ w4) {
    __shared__ float tile[32][33];
    const float* src;
    switch (blockIdx.z) {
        case 0: src = w0; break;
        case 1: src = w1; break;
        case 2: src = w2; break;
        case 3: src = w3; break;
        default: src = w4; break;
    }
    int i0 = blockIdx.x * 32;   // column of original (input dim)
    int j0 = blockIdx.y * 32;   // row of original (output neuron)
    int tx = threadIdx.x, ty = threadIdx.y;
    tile[ty][tx] = src[(j0 + ty) * H + (i0 + tx)];
    __syncthreads();
    g_wt[(size_t)blockIdx.z * MATF + (size_t)(i0 + ty) * H + (j0 + tx)] = tile[tx][ty];
    if (blockIdx.x == 0 && ty < HPAD) {
        int jz = blockIdx.y * 32 + tx;
        g_wt[(size_t)blockIdx.z * MATF + (size_t)(H + ty) * H + jz] = 0.0f;
    }
}

// ---------------------------------------------------------------------------
// Per-sample event walk: acc = sequential RN-FADD over fired indices
// (ascending). cnt % 8 == 0 (padded with i = H -> w = +0 -> exact no-op).
// Bit-exact vs the dense fma chain because spike values are exactly 0/1.
// ---------------------------------------------------------------------------
__device__ __forceinline__ float walk(const ushort_t* __restrict__ lst, int cnt,
                                      const float* __restrict__ wcol) {
    float acc = 0.0f;
    for (int k = 0; k < cnt; k += 8) {
        uint4 v = *(const uint4*)(lst + k);
        unsigned i0 = v.x & 0xFFFFu, i1 = v.x >> 16;
        unsigned i2 = v.y & 0xFFFFu, i3 = v.y >> 16;
        unsigned i4 = v.z & 0xFFFFu, i5 = v.z >> 16;
        unsigned i6 = v.w & 0xFFFFu, i7 = v.w >> 16;
        float w0 = __ldg(wcol + (size_t)i0 * H);
        float w1 = __ldg(wcol + (size_t)i1 * H);
        float w2 = __ldg(wcol + (size_t)i2 * H);
        float w3 = __ldg(wcol + (size_t)i3 * H);
        float w4 = __ldg(wcol + (size_t)i4 * H);
        float w5 = __ldg(wcol + (size_t)i5 * H);
        float w6 = __ldg(wcol + (size_t)i6 * H);
        float w7 = __ldg(wcol + (size_t)i7 * H);
        acc = __fadd_rn(acc, w0);
        acc = __fadd_rn(acc, w1);
        acc = __fadd_rn(acc, w2);
        acc = __fadd_rn(acc, w3);
        acc = __fadd_rn(acc, w4);
        acc = __fadd_rn(acc, w5);
        acc = __fadd_rn(acc, w6);
        acc = __fadd_rn(acc, w7);
    }
    return acc;
}

// ---------------------------------------------------------------------------
// Main persistent SRNN kernel, per-sample event-driven.
// One block = 4 samples, thread j = neuron j. No spike float buffers at all:
// own spikes live in registers; matvecs walk per-sample fired lists.
// ---------------------------------------------------------------------------
__global__ void __launch_bounds__(NTHR, 1) srnn_kernel(
    const float* __restrict__ x,
    const float* __restrict__ i2h1_w, const float* __restrict__ i2h1_b,
    const float* __restrict__ h2h1_b,
    const float* __restrict__ i2h2_b, const float* __restrict__ h2h2_b,
    const float* __restrict__ i2h3_b, const float* __restrict__ h2h3_b,
    const float* __restrict__ h2o_w,  const float* __restrict__ h2o_b,
    const float* __restrict__ tau_adp_h1, const float* __restrict__ tau_adp_h2,
    const float* __restrict__ tau_adp_h3,
    const float* __restrict__ tau_m_h1,   const float* __restrict__ tau_m_h2,
    const float* __restrict__ tau_m_h3,
    float* __restrict__ out)
{
    // lists[buf][sample][H]: buf = 2*layer + parity
    __shared__ ushort_t lists[6 * SPB * H];
    __shared__ int cnts[6 * SPB];
    __shared__ int wcnt[NWARP];
    __shared__ float stage[SPB * H];

    const int j    = threadIdx.x;
    const int warp = j >> 5, lane = j & 31;
    const unsigned lanemask_lt = (1u << lane) - 1u;
    const int smp0 = blockIdx.x * SPB;

    int cur = 0;
    if (j < 6 * SPB) cnts[j] = 0;

    const float a1 = xla_cephes_expf(__fdiv_rn(-1.0f, tau_m_h1[j]));
    const float a2 = xla_cephes_expf(__fdiv_rn(-1.0f, tau_m_h2[j]));
    const float a3 = xla_cephes_expf(__fdiv_rn(-1.0f, tau_m_h3[j]));
    const float r1 = xla_cephes_expf(__fdiv_rn(-1.0f, tau_adp_h1[j]));
    const float r2 = xla_cephes_expf(__fdiv_rn(-1.0f, tau_adp_h2[j]));
    const float r3 = xla_cephes_expf(__fdiv_rn(-1.0f, tau_adp_h3[j]));
    const float oma1 = __fsub_rn(1.0f, a1), oma2 = __fsub_rn(1.0f, a2),
                oma3 = __fsub_rn(1.0f, a3);
    const float omr1 = __fsub_rn(1.0f, r1), omr2 = __fsub_rn(1.0f, r2),
                omr3 = __fsub_rn(1.0f, r3);

    const float bi1 = i2h1_b[j], bh1 = h2h1_b[j];
    const float bi2 = i2h2_b[j], bh2 = h2h2_b[j];
    const float bi3 = i2h3_b[j], bh3 = h2h3_b[j];

    float wi1[INW];
    {
        float4 wa = *(const float4*)(i2h1_w + j * INW);
        float4 wb = *(const float4*)(i2h1_w + j * INW + 4);
        wi1[0] = wa.x; wi1[1] = wa.y; wi1[2] = wa.z; wi1[3] = wa.w;
        wi1[4] = wb.x; wi1[5] = wb.y; wi1[6] = wb.z; wi1[7] = wb.w;
    }

    float m1[SPB], m2[SPB], m3[SPB], b1[SPB], b2[SPB], b3[SPB], c3[SPB];
    float s1o[SPB], s2o[SPB], s3o[SPB];
#pragma unroll
    for (int s = 0; s < SPB; ++s) {
        m1[s] = m2[s] = m3[s] = 0.0f;
        b1[s] = b2[s] = b3[s] = 0.01f;
        c3[s] = 0.0f;
        s1o[s] = s2o[s] = s3o[s] = 0.0f;
    }

    const float* wt_h2h1 = g_wt + 0 * (size_t)MATF + j;
    const float* wt_i2h2 = g_wt + 1 * (size_t)MATF + j;
    const float* wt_h2h2 = g_wt + 2 * (size_t)MATF + j;
    const float* wt_i2h3 = g_wt + 3 * (size_t)MATF + j;
    const float* wt_h2h3 = g_wt + 4 * (size_t)MATF + j;

    __syncthreads();

    for (int t = 0; t < TSTEPS; ++t) {
        const int st = (t * INW < TSTEPS - INW) ? t * INW : (NPIX - INW);

        const int b1c = 0 + cur, b1n = 0 + (cur ^ 1);
        const int b2c = 2 + cur, b2n = 2 + (cur ^ 1);
        const int b3c = 4 + cur, b3n = 4 + (cur ^ 1);

        float snew[SPB];

        // ================= layer 1 =================
        {
            float dh[SPB];
#pragma unroll
            for (int s = 0; s < SPB; ++s)
                dh[s] = walk(lists + (b1c * SPB + s) * H, cnts[b1c * SPB + s],
                             wt_h2h1);

            const float* xb = x + (size_t)smp0 * NPIX + st;
#pragma unroll
            for (int s = 0; s < SPB; ++s) {
                float4 xa = *(const float4*)(xb + (size_t)s * NPIX);
                float4 xc = *(const float4*)(xb + (size_t)s * NPIX + 4);
                float dx = __fmaf_rn(xa.x, wi1[0], 0.0f);
                dx = __fmaf_rn(xa.y, wi1[1], dx);
                dx = __fmaf_rn(xa.z, wi1[2], dx);
                dx = __fmaf_rn(xa.w, wi1[3], dx);
                dx = __fmaf_rn(xc.x, wi1[4], dx);
                dx = __fmaf_rn(xc.y, wi1[5], dx);
                dx = __fmaf_rn(xc.z, wi1[6], dx);
                dx = __fmaf_rn(xc.w, wi1[7], dx);
                float h = __fadd_rn(__fadd_rn(__fadd_rn(dx, bi1), dh[s]), bh1);
                alif_step(h, m1[s], b1[s], s1o[s], a1, oma1, r1, omr1, snew[s]);
            }
        }
        // build per-sample lists for buffer b1n
        {
            unsigned mk[SPB];
#pragma unroll
            for (int s = 0; s < SPB; ++s)
                mk[s] = __ballot_sync(0xffffffffu, snew[s] > 0.0f);
            if (lane == 0)
                wcnt[warp] = __popc(mk[0]) | (__popc(mk[1]) << 8)
                           | (__popc(mk[2]) << 16) | (__popc(mk[3]) << 24);
            __syncthreads();
            int base[SPB] = {0, 0, 0, 0}, tot[SPB] = {0, 0, 0, 0};
#pragma unroll
            for (int w = 0; w < NWARP; ++w) {
                unsigned c = (unsigned)wcnt[w];
#pragma unroll
                for (int s = 0; s < SPB; ++s) {
                    int cs = (c >> (8 * s)) & 0xFF;
                    if (w < warp) base[s] += cs;
                    tot[s] += cs;
                }
            }
            ushort_t* L = lists + b1n * SPB * H;
#pragma unroll
            for (int s = 0; s < SPB; ++s)
                if ((mk[s] >> lane) & 1u)
                    L[s * H + base[s] + __popc(mk[s] & lanemask_lt)] = (ushort_t)j;
            if (j < SPB) {
                int tt = tot[j];
                int padded = (tt + 7) & ~7;
                for (int k = tt; k < padded; ++k) L[j * H + k] = (ushort_t)H;
                cnts[b1n * SPB + j] = padded;
            }
#pragma unroll
            for (int s = 0; s < SPB; ++s) s1o[s] = snew[s];
            __syncthreads();
        }

        // ================= layer 2 =================
        {
            float dI[SPB], dH[SPB];
#pragma unroll
            for (int s = 0; s < SPB; ++s)
                dI[s] = walk(lists + (b1n * SPB + s) * H, cnts[b1n * SPB + s],
                             wt_i2h2);
#pragma unroll
            for (int s = 0; s < SPB; ++s)
                dH[s] = walk(lists + (b2c * SPB + s) * H, cnts[b2c * SPB + s],
                             wt_h2h2);
#pragma unroll
            for (int s = 0; s < SPB; ++s) {
                float h = __fadd_rn(__fadd_rn(__fadd_rn(dI[s], bi2), dH[s]), bh2);
                alif_step(h, m2[s], b2[s], s2o[s], a2, oma2, r2, omr2, snew[s]);
            }
        }
        {
            unsigned mk[SPB];
#pragma unroll
            for (int s = 0; s < SPB; ++s)
                mk[s] = __ballot_sync(0xffffffffu, snew[s] > 0.0f);
            if (lane == 0)
                wcnt[warp] = __popc(mk[0]) | (__popc(mk[1]) << 8)
                           | (__popc(mk[2]) << 16) | (__popc(mk[3]) << 24);
            __syncthreads();
            int base[SPB] = {0, 0, 0, 0}, tot[SPB] = {0, 0, 0, 0};
#pragma unroll
            for (int w = 0; w < NWARP; ++w) {
                unsigned c = (unsigned)wcnt[w];
#pragma unroll
                for (int s = 0; s < SPB; ++s) {
                    int cs = (c >> (8 * s)) & 0xFF;
                    if (w < warp) base[s] += cs;
                    tot[s] += cs;
                }
            }
            ushort_t* L = lists + b2n * SPB * H;
#pragma unroll
            for (int s = 0; s < SPB; ++s)
                if ((mk[s] >> lane) & 1u)
                    L[s * H + base[s] + __popc(mk[s] & lanemask_lt)] = (ushort_t)j;
            if (j < SPB) {
                int tt = tot[j];
                int padded = (tt + 7) & ~7;
                for (int k = tt; k < padded; ++k) L[j * H + k] = (ushort_t)H;
                cnts[b2n * SPB + j] = padded;
            }
#pragma unroll
            for (int s = 0; s < SPB; ++s) s2o[s] = snew[s];
            __syncthreads();
        }

        // ================= layer 3 =================
        {
            float dI[SPB], dH[SPB];
#pragma unroll
            for (int s = 0; s < SPB; ++s)
                dI[s] = walk(lists + (b2n * SPB + s) * H, cnts[b2n * SPB + s],
                             wt_i2h3);
#pragma unroll
            for (int s = 0; s < SPB; ++s)
                dH[s] = walk(lists + (b3c * SPB + s) * H, cnts[b3c * SPB + s],
                             wt_h2h3);
#pragma unroll
            for (int s = 0; s < SPB; ++s) {
                float h = __fadd_rn(__fadd_rn(__fadd_rn(dI[s], bi3), dH[s]), bh3);
                alif_step(h, m3[s], b3[s], s3o[s], a3, oma3, r3, omr3, snew[s]);
            }
        }
        {
            unsigned mk[SPB];
#pragma unroll
            for (int s = 0; s < SPB; ++s)
                mk[s] = __ballot_sync(0xffffffffu, snew[s] > 0.0f);
            if (lane == 0)
                wcnt[warp] = __popc(mk[0]) | (__popc(mk[1]) << 8)
                           | (__popc(mk[2]) << 16) | (__popc(mk[3]) << 24);
            __syncthreads();
            int base[SPB] = {0, 0, 0, 0}, tot[SPB] = {0, 0, 0, 0};
#pragma unroll
            for (int w = 0; w < NWARP; ++w) {
                unsigned c = (unsigned)wcnt[w];
#pragma unroll
                for (int s = 0; s < SPB; ++s) {
                    int cs = (c >> (8 * s)) & 0xFF;
                    if (w < warp) base[s] += cs;
                    tot[s] += cs;
                }
            }
            ushort_t* L = lists + b3n * SPB * H;
#pragma unroll
            for (int s = 0; s < SPB; ++s)
                if ((mk[s] >> lane) & 1u)
                    L[s * H + base[s] + __popc(mk[s] & lanemask_lt)] = (ushort_t)j;
            if (j < SPB) {
                int tt = tot[j];
                int padded = (tt + 7) & ~7;
                for (int k = tt; k < padded; ++k) L[j * H + k] = (ushort_t)H;
                cnts[b3n * SPB + j] = padded;
            }
#pragma unroll
            for (int s = 0; s < SPB; ++s) {
                s3o[s] = snew[s];
                c3[s] += snew[s];
            }
            __syncthreads();
        }

        cur ^= 1;
    }

    // ======== output: out[smp][o] = (sum_j c3[smp][j]*W[o][j]) / T + b[o] ========
    __syncthreads();
#pragma unroll
    for (int s = 0; s < SPB; ++s) stage[s * H + j] = c3[s];
    __syncthreads();

    for (int pair = warp; pair < SPB * OUTN; pair += NWARP) {
        int s = pair / OUTN, o = pair % OUTN;
        float sum = 0.0f;
        for (int jj = lane; jj < H; jj += 32)
            sum += stage[s * H + jj] * __ldg(h2o_w + o * H + jj);
#pragma unroll
        for (int off = 16; off > 0; off >>= 1)
            sum += __shfl_down_sync(0xffffffffu, sum, off);
        if (lane == 0)
            out[(size_t)(smp0 + s) * OUTN + o] = sum / (float)TSTEPS + h2o_b[o];
    }
}

// ---------------------------------------------------------------------------
extern "C" void kernel_launch(void* const* d_in, const int* in_sizes, int n_in,
                              void* d_out, int out_size) {
    (void)in_sizes; (void)n_in; (void)out_size;
    const float* x          = (const float*)d_in[0];
    const float* i2h1_w     = (const float*)d_in[1];
    const float* i2h1_b     = (const float*)d_in[2];
    const float* h2h1_w     = (const float*)d_in[3];
    const float* h2h1_b     = (const float*)d_in[4];
    const float* i2h2_w     = (const float*)d_in[5];
    const float* i2h2_b     = (const float*)d_in[6];
    const float* h2h2_w     = (const float*)d_in[7];
    const float* h2h2_b     = (const float*)d_in[8];
    const float* i2h3_w     = (const float*)d_in[9];
    const float* i2h3_b     = (const float*)d_in[10];
    const float* h2h3_w     = (const float*)d_in[11];
    const float* h2h3_b     = (const float*)d_in[12];
    const float* h2o_w      = (const float*)d_in[13];
    const float* h2o_b      = (const float*)d_in[14];
    const float* tau_adp_h1 = (const float*)d_in[15];
    const float* tau_adp_h2 = (const float*)d_in[16];
    const float* tau_adp_h3 = (const float*)d_in[17];
    const float* tau_m_h1   = (const float*)d_in[18];
    const float* tau_m_h2   = (const float*)d_in[19];
    const float* tau_m_h3   = (const float*)d_in[20];
    float* out = (float*)d_out;

    transpose5_kernel<<<dim3(16, 16, 5), dim3(32, 32)>>>(h2h1_w, i2h2_w, h2h2_w,
                                                         i2h3_w, h2h3_w);

    srnn_kernel<<<NBLK, NTHR>>>(
        x, i2h1_w, i2h1_b, h2h1_b, i2h2_b, h2h2_b, i2h3_b, h2h3_b,
        h2o_w, h2o_b, tau_adp_h1, tau_adp_h2, tau_adp_h3,
        tau_m_h1, tau_m_h2, tau_m_h3, out);
}